// round 8
// baseline (speedup 1.0000x reference)
#include <cuda_runtime.h>

// Bilateral filter: B=8, C=3, H=W=512, K=5, sigma_s=2.0, sigma_r=0.1
//
// R8: same pairwise-shared-exp algorithm (4x4 patch/thread, 294 EX2/16px,
// baked log2-spatial immediates, exactly-1.0 center tap). Register diet:
// NO row ring — only the current window row lives in registers; partner
// rows (r-1, r-2) are re-read from smem as transients. Persistent state
// ~46 regs -> launch_bounds(128,10) caps at 51 regs = 10 CTAs/SM = 40
// warps (was 32). LDS pipe has 5x headroom; MUFU hiding + smaller tail
// (waves 2.59 -> 2.08) are the levers.

#define HW   512
#define TILEW 64
#define TILEH 32
#define SROW 68
#define C1F  8.4932165750422091f
#define LSOF(dsq) (-0.18033688011112043f * (float)(dsq))   // log2(exp(-dsq/8))

__device__ __forceinline__ float ex2a(float v) {
    float y;
    asm("ex2.approx.ftz.f32 %0, %1;" : "=f"(y) : "f"(v));
    return y;
}

__device__ __forceinline__ int reflect512(int g) {
    g = (g < 0) ? -g : g;
    return (g > 511) ? (1022 - g) : g;
}

// ownership of a window-local coordinate (window is 8x8, owned core is 2..5)
#define OWN(rr,cc) ((rr) >= 2 && (rr) <= 5 && (cc) >= 2 && (cc) <= 5)

// one unordered pair; all index args compile-time constants after unrolling
#define PAIR(va, vb, ra, ca, rb, cb, di, dj) do {                              \
    const bool oa_ = OWN(ra, ca), ob_ = OWN(rb, cb);                           \
    if (oa_ || ob_) {                                                          \
        float t_ = (va) - (vb);                                                \
        float w_ = ex2a(fmaf(t_, -t_, LSOF((di)*(di)+(dj)*(dj))));             \
        if (oa_) { const int ia_ = ((ra)-2)*4 + ((ca)-2);                      \
                   wsum[ia_] += w_; acc[ia_] = fmaf(w_, (vb), acc[ia_]); }     \
        if (ob_) { const int ib_ = ((rb)-2)*4 + ((cb)-2);                      \
                   wsum[ib_] += w_; acc[ib_] = fmaf(w_, (va), acc[ib_]); }     \
    }                                                                          \
} while (0)

#define LOADROW(dstv, rr) do {                                                 \
    float4 a_ = *(const float4*)&tile[(R0 + (rr)) * SROW + C0];                \
    float4 b_ = *(const float4*)&tile[(R0 + (rr)) * SROW + C0 + 4];            \
    (dstv)[0] = a_.x; (dstv)[1] = a_.y; (dstv)[2] = a_.z; (dstv)[3] = a_.w;    \
    (dstv)[4] = b_.x; (dstv)[5] = b_.y; (dstv)[6] = b_.z; (dstv)[7] = b_.w;    \
} while (0)

__global__ __launch_bounds__(128, 10)
void bilateral_kernel(const float* __restrict__ x,
                      float* __restrict__ out) {
    __shared__ float tile[36 * SROW];

    const int bx = blockIdx.x * TILEW;
    const int by = blockIdx.y * TILEH;
    const float* __restrict__ src = x   + (size_t)blockIdx.z * (HW * HW);
    float* __restrict__       dst = out + (size_t)blockIdx.z * (HW * HW);

    const int tx  = threadIdx.x;         // 0..15
    const int ty  = threadIdx.y;         // 0..7
    const int tid = ty * 16 + tx;

    const bool interior = (bx != 0) && (bx != HW - TILEW) &&
                          (by != 0) && (by != HW - TILEH);

    if (interior) {
        const float* base = src + (size_t)(by - 2) * HW + (bx - 2);
        const int c6 = tid & 63;
        const int r2 = tid >> 6;          // 0..1
        #pragma unroll
        for (int it = 0; it < 18; it++) {
            const int r = it * 2 + r2;
            tile[r * SROW + c6] = base[r * HW + c6] * C1F;
        }
        #pragma unroll
        for (int it = 0; it < 2; it++) {
            const int idx = it * 128 + tid;
            if (idx < 144) {
                const int r = idx >> 2;
                const int c = 64 + (idx & 3);
                tile[r * SROW + c] = base[r * HW + c] * C1F;
            }
        }
    } else {
        for (int i = tid; i < 36 * 68; i += 128) {
            const int r = i / 68;
            const int c = i - r * 68;
            tile[r * SROW + c] = src[reflect512(by + r - 2) * HW +
                                     reflect512(bx + c - 2)] * C1F;
        }
    }
    __syncthreads();

    const int R0 = 4 * ty;   // smem row of window origin (0..28)
    const int C0 = 4 * tx;   // smem col of window origin (0..60)

    float wsum[16], acc[16];
    #pragma unroll
    for (int i = 0; i < 16; i++) { wsum[i] = 0.0f; acc[i] = 0.0f; }

    #pragma unroll
    for (int r = 0; r < 8; r++) {
        float cur[8];
        LOADROW(cur, r);

        // ---- center taps: weight is exactly 1.0, no exp
        if (r >= 2 && r <= 5) {
            #pragma unroll
            for (int c = 2; c <= 5; c++) {
                const int ia = (r - 2) * 4 + (c - 2);
                wsum[ia] += 1.0f;
                acc[ia]  += cur[c];
            }
        }

        // ---- di=0 pairs (within row r)
        if (r >= 2 && r <= 5) {
            #pragma unroll
            for (int c = 1; c <= 5; c++)       // dj = 1
                PAIR(cur[c], cur[c+1], r, c, r, c+1, 0, 1);
            #pragma unroll
            for (int c = 0; c <= 5; c++)       // dj = 2
                PAIR(cur[c], cur[c+2], r, c, r, c+2, 0, 2);
        }

        // ---- di=1 pairs: partner row r-1 re-read from smem (transient)
        if (r >= 1) {
            float p1[8];
            LOADROW(p1, r - 1);
            #pragma unroll
            for (int dj = -2; dj <= 2; dj++) {
                #pragma unroll
                for (int c = 0; c < 8; c++) {
                    const int cb = c + dj;
                    if (cb < 0 || cb > 7) continue;
                    PAIR(p1[c], cur[cb], r-1, c, r, cb, 1, dj);
                }
            }
        }

        // ---- di=2 pairs: partner row r-2 re-read from smem (transient)
        if (r >= 2) {
            float p2[8];
            LOADROW(p2, r - 2);
            #pragma unroll
            for (int dj = -2; dj <= 2; dj++) {
                #pragma unroll
                for (int c = 0; c < 8; c++) {
                    const int cb = c + dj;
                    if (cb < 0 || cb > 7) continue;
                    PAIR(p2[c], cur[cb], r-2, c, r, cb, 2, dj);
                }
            }
        }
    }

    // ---- normalize, un-scale by 1/C1, store
    const float INV = 1.0f / C1F;
    #pragma unroll
    for (int pr = 0; pr < 4; pr++) {
        float4 o;
        o.x = __fdividef(acc[pr*4 + 0], wsum[pr*4 + 0]) * INV;
        o.y = __fdividef(acc[pr*4 + 1], wsum[pr*4 + 1]) * INV;
        o.z = __fdividef(acc[pr*4 + 2], wsum[pr*4 + 2]) * INV;
        o.w = __fdividef(acc[pr*4 + 3], wsum[pr*4 + 3]) * INV;
        *(float4*)&dst[(by + R0 + pr) * HW + bx + C0] = o;
    }
}

extern "C" void kernel_launch(void* const* d_in, const int* in_sizes, int n_in,
                              void* d_out, int out_size) {
    const float* x = (const float*)d_in[0];  // (8,3,512,512)
    float* out     = (float*)d_out;

    dim3 block(16, 8);
    dim3 grid(HW / TILEW, HW / TILEH, 24);   // 8 x 16 x 24 = 3072 CTAs
    bilateral_kernel<<<grid, block>>>(x, out);
}

// round 9
// speedup vs baseline: 1.1899x; 1.1899x over previous
#include <cuda_runtime.h>

// Bilateral filter: B=8, C=3, H=W=512, K=5, sigma_s=2.0, sigma_r=0.1
//
// R9: R7's algorithm unchanged (4x4 patch/thread, 294 shared-exp pairs per
// 16 px, baked log2-spatial immediates, exactly-1.0 center, di=1 register
// ring + di=2 smem reload). Repackaged into 64-thread CTAs on 32x32 tiles:
// 16 CTAs/SM (64 regs x 64 thr x 16 = 64K regs exactly) = 16 independent
// streams to fill row-load/tile-load bubbles + half the work quantum =
// half the end-of-launch tail.

#define HW   512
#define TILE 32
#define SROW 36
#define C1F  8.4932165750422091f
#define LSOF(dsq) (-0.18033688011112043f * (float)(dsq))   // log2(exp(-dsq/8))

__device__ __forceinline__ float ex2a(float v) {
    float y;
    asm("ex2.approx.ftz.f32 %0, %1;" : "=f"(y) : "f"(v));
    return y;
}

__device__ __forceinline__ int reflect512(int g) {
    g = (g < 0) ? -g : g;
    return (g > 511) ? (1022 - g) : g;
}

// ownership of a window-local coordinate (window is 8x8, owned core is 2..5)
#define OWN(rr,cc) ((rr) >= 2 && (rr) <= 5 && (cc) >= 2 && (cc) <= 5)

// one unordered pair; all index args compile-time constants after unrolling
#define PAIR(va, vb, ra, ca, rb, cb, di, dj) do {                              \
    const bool oa_ = OWN(ra, ca), ob_ = OWN(rb, cb);                           \
    if (oa_ || ob_) {                                                          \
        float t_ = (va) - (vb);                                                \
        float w_ = ex2a(fmaf(t_, -t_, LSOF((di)*(di)+(dj)*(dj))));             \
        if (oa_) { const int ia_ = ((ra)-2)*4 + ((ca)-2);                      \
                   wsum[ia_] += w_; acc[ia_] = fmaf(w_, (vb), acc[ia_]); }     \
        if (ob_) { const int ib_ = ((rb)-2)*4 + ((cb)-2);                      \
                   wsum[ib_] += w_; acc[ib_] = fmaf(w_, (va), acc[ib_]); }     \
    }                                                                          \
} while (0)

__global__ __launch_bounds__(64, 16)
void bilateral_kernel(const float* __restrict__ x,
                      float* __restrict__ out) {
    __shared__ float tile[36 * SROW];

    const int bx = blockIdx.x * TILE;
    const int by = blockIdx.y * TILE;
    const float* __restrict__ src = x   + (size_t)blockIdx.z * (HW * HW);
    float* __restrict__       dst = out + (size_t)blockIdx.z * (HW * HW);

    const int tid = threadIdx.x;          // 0..63

    const bool interior = (bx != 0) && (bx != HW - TILE) &&
                          (by != 0) && (by != HW - TILE);

    if (interior) {
        const float* base = src + (size_t)(by - 2) * HW + (bx - 2);
        const int c5 = tid & 31;
        const int r2 = tid >> 5;          // 0..1
        // main region: 36 rows x cols 0..31 (18 passes of 2 rows)
        #pragma unroll
        for (int it = 0; it < 18; it++) {
            const int r = it * 2 + r2;
            tile[r * SROW + c5] = base[r * HW + c5] * C1F;
        }
        // strip: cols 32..35, 36 rows (144 elems, 3 guarded passes of 64)
        #pragma unroll
        for (int it = 0; it < 3; it++) {
            const int idx = it * 64 + tid;
            if (idx < 144) {
                const int r = idx >> 2;
                const int c = 32 + (idx & 3);
                tile[r * SROW + c] = base[r * HW + c] * C1F;
            }
        }
    } else {
        for (int i = tid; i < 36 * 36; i += 64) {
            const int r = i / 36;
            const int c = i - r * 36;
            tile[r * SROW + c] = src[reflect512(by + r - 2) * HW +
                                     reflect512(bx + c - 2)] * C1F;
        }
    }
    __syncthreads();

    const int R0 = 4 * (tid >> 3);   // smem row of window origin (0..28)
    const int C0 = 4 * (tid & 7);    // smem col of window origin (0..28)

    float wsum[16], acc[16];
    #pragma unroll
    for (int i = 0; i < 16; i++) { wsum[i] = 0.0f; acc[i] = 0.0f; }

    float rows[2][8];   // 2-row ping-pong ring (constant indices after unroll)

    #pragma unroll
    for (int r = 0; r < 8; r++) {
        const int cr = r & 1;

        // load window row r: cols C0..C0+7, two aligned float4 (conflict-free)
        {
            float4 a = *(const float4*)&tile[(R0 + r) * SROW + C0];
            float4 b = *(const float4*)&tile[(R0 + r) * SROW + C0 + 4];
            rows[cr][0] = a.x; rows[cr][1] = a.y;
            rows[cr][2] = a.z; rows[cr][3] = a.w;
            rows[cr][4] = b.x; rows[cr][5] = b.y;
            rows[cr][6] = b.z; rows[cr][7] = b.w;
        }

        // ---- center taps: weight is exactly 1.0, no exp
        if (r >= 2 && r <= 5) {
            #pragma unroll
            for (int c = 2; c <= 5; c++) {
                const int ia = (r - 2) * 4 + (c - 2);
                wsum[ia] += 1.0f;
                acc[ia]  += rows[cr][c];
            }
        }

        // ---- di=0 pairs (within row r)
        if (r >= 2 && r <= 5) {
            #pragma unroll
            for (int c = 1; c <= 5; c++)       // dj = 1
                PAIR(rows[cr][c], rows[cr][c+1], r, c, r, c+1, 0, 1);
            #pragma unroll
            for (int c = 0; c <= 5; c++)       // dj = 2
                PAIR(rows[cr][c], rows[cr][c+2], r, c, r, c+2, 0, 2);
        }

        // ---- di=1 pairs: rows (r-1, r) from the ring
        if (r >= 1) {
            const int pr = (r - 1) & 1;
            #pragma unroll
            for (int dj = -2; dj <= 2; dj++) {
                #pragma unroll
                for (int c = 0; c < 8; c++) {
                    const int cb = c + dj;
                    if (cb < 0 || cb > 7) continue;
                    PAIR(rows[pr][c], rows[cr][cb], r-1, c, r, cb, 1, dj);
                }
            }
        }

        // ---- di=2 pairs: partner row r-2 re-read from smem (transient regs)
        if (r >= 2) {
            float p2[8];
            {
                float4 a = *(const float4*)&tile[(R0 + r - 2) * SROW + C0];
                float4 b = *(const float4*)&tile[(R0 + r - 2) * SROW + C0 + 4];
                p2[0] = a.x; p2[1] = a.y; p2[2] = a.z; p2[3] = a.w;
                p2[4] = b.x; p2[5] = b.y; p2[6] = b.z; p2[7] = b.w;
            }
            #pragma unroll
            for (int dj = -2; dj <= 2; dj++) {
                #pragma unroll
                for (int c = 0; c < 8; c++) {
                    const int cb = c + dj;
                    if (cb < 0 || cb > 7) continue;
                    PAIR(p2[c], rows[cr][cb], r-2, c, r, cb, 2, dj);
                }
            }
        }
    }

    // ---- normalize, un-scale by 1/C1, store
    const float INV = 1.0f / C1F;
    #pragma unroll
    for (int pr = 0; pr < 4; pr++) {
        float4 o;
        o.x = __fdividef(acc[pr*4 + 0], wsum[pr*4 + 0]) * INV;
        o.y = __fdividef(acc[pr*4 + 1], wsum[pr*4 + 1]) * INV;
        o.z = __fdividef(acc[pr*4 + 2], wsum[pr*4 + 2]) * INV;
        o.w = __fdividef(acc[pr*4 + 3], wsum[pr*4 + 3]) * INV;
        *(float4*)&dst[(by + R0 + pr) * HW + bx + C0] = o;
    }
}

extern "C" void kernel_launch(void* const* d_in, const int* in_sizes, int n_in,
                              void* d_out, int out_size) {
    const float* x = (const float*)d_in[0];  // (8,3,512,512)
    float* out     = (float*)d_out;

    dim3 block(64);
    dim3 grid(HW / TILE, HW / TILE, 24);   // 16 x 16 x 24 = 6144 CTAs
    bilateral_kernel<<<grid, block>>>(x, out);
}